// round 15
// baseline (speedup 1.0000x reference)
#include <cuda_runtime.h>
#include <math.h>
#include <stdint.h>

#define NN 50000
#define EE 800000
#define FIN 10
#define HH 64
#define LL 3

__device__ float d_hA[NN * HH];
__device__ float d_hB[NN * HH];
__device__ int   d_deg[NN];
__device__ int   d_off[NN];            // bucket start per node (unordered)
__device__ int   d_cur[NN];
__device__ int   d_total;
__device__ int   d_srcp[EE];           // src node per CSR slot
__device__ int   d_perm[EE];           // original edge id per CSR slot
__device__ float d_gcsr[LL * EE];      // gates in CSR order, per layer

// ---------------------------------------------------------------------------
// packed f32x2 helpers
// ---------------------------------------------------------------------------
__device__ __forceinline__ void ldsv2u64(uint32_t addr,
                                         unsigned long long& a,
                                         unsigned long long& b) {
    asm volatile("ld.shared.v2.u64 {%0,%1}, [%2];"
                 : "=l"(a), "=l"(b) : "r"(addr));
}
__device__ __forceinline__ void ffma2(unsigned long long& d,
                                      unsigned long long a,
                                      unsigned long long b) {
    asm("fma.rn.f32x2 %0, %1, %2, %0;" : "+l"(d) : "l"(a), "l"(b));
}
__device__ __forceinline__ float pairsum(unsigned long long v) {
    uint32_t lo, hi;
    asm("mov.b64 {%0,%1}, %2;" : "=r"(lo), "=r"(hi) : "l"(v));
    return __uint_as_float(lo) + __uint_as_float(hi);
}

// ---------------------------------------------------------------------------
// h = relu(x @ Wp + bp)
// ---------------------------------------------------------------------------
__global__ void proj_kernel(const float* __restrict__ x,
                            const float* __restrict__ Wp,
                            const float* __restrict__ bp) {
    __shared__ float Ws[FIN * HH];
    __shared__ float bs[HH];
    for (int i = threadIdx.x; i < FIN * HH; i += blockDim.x) Ws[i] = Wp[i];
    if (threadIdx.x < HH) bs[threadIdx.x] = bp[threadIdx.x];
    __syncthreads();

    int idx = blockIdx.x * blockDim.x + threadIdx.x;
    if (idx >= NN * HH) return;
    int i = idx >> 6;
    int j = idx & 63;
    float acc = bs[j];
#pragma unroll
    for (int k = 0; k < FIN; k++) acc = fmaf(x[i * FIN + k], Ws[k * HH + j], acc);
    d_hA[idx] = fmaxf(acc, 0.f);
}

// ---------------------------------------------------------------------------
// CSR build: count (x4 ILP) -> alloc (warp-aggregated atomic) -> fill (x4 ILP)
// ---------------------------------------------------------------------------
#define QS (EE / 4)    // 200000

__global__ void count_kernel(const int* __restrict__ ei) {
    int t = blockIdx.x * blockDim.x + threadIdx.x;
    if (t >= QS) return;
    int d0 = ei[EE + t];
    int d1 = ei[EE + t + QS];
    int d2 = ei[EE + t + 2 * QS];
    int d3 = ei[EE + t + 3 * QS];
    atomicAdd(&d_deg[d0], 1);
    atomicAdd(&d_deg[d1], 1);
    atomicAdd(&d_deg[d2], 1);
    atomicAdd(&d_deg[d3], 1);
}

__global__ void alloc_kernel() {
    int nd = blockIdx.x * blockDim.x + threadIdx.x;
    int lane = threadIdx.x & 31;
    int deg = (nd < NN) ? d_deg[nd] : 0;
    int sc = deg;
#pragma unroll
    for (int o = 1; o < 32; o <<= 1) {
        int v = __shfl_up_sync(0xffffffffu, sc, o);
        if (lane >= o) sc += v;
    }
    int wsum = __shfl_sync(0xffffffffu, sc, 31);
    int base = 0;
    if (lane == 31) base = atomicAdd(&d_total, wsum);
    base = __shfl_sync(0xffffffffu, base, 31);
    if (nd < NN) {
        int excl = base + sc - deg;
        d_off[nd] = excl;
        d_cur[nd] = excl;
    }
}

__global__ void fill_kernel(const int* __restrict__ ei) {
    int t = blockIdx.x * blockDim.x + threadIdx.x;
    if (t >= QS) return;
    int d0 = ei[EE + t];
    int d1 = ei[EE + t + QS];
    int d2 = ei[EE + t + 2 * QS];
    int d3 = ei[EE + t + 3 * QS];
    int p0 = atomicAdd(&d_cur[d0], 1);
    int p1 = atomicAdd(&d_cur[d1], 1);
    int p2 = atomicAdd(&d_cur[d2], 1);
    int p3 = atomicAdd(&d_cur[d3], 1);
    d_perm[p0] = t;
    d_perm[p1] = t + QS;
    d_perm[p2] = t + 2 * QS;
    d_perm[p3] = t + 3 * QS;
}

// ---------------------------------------------------------------------------
// Gates for all 3 layers (CSR order) + srcp materialization (coalesced write).
// ---------------------------------------------------------------------------
__global__ void gatecsr_kernel(const int* __restrict__ ei,
                               const float* __restrict__ ea,
                               const float* __restrict__ ew1,
                               const float* __restrict__ eb1,
                               const float* __restrict__ ew2,
                               const float* __restrict__ eb2) {
    __shared__ float W1[LL * 3 * 16];
    __shared__ float B1[LL * 16];
    __shared__ float W2[LL * 16];
    __shared__ float B2[LL];
    for (int i = threadIdx.x; i < LL * 3 * 16; i += blockDim.x) W1[i] = ew1[i];
    if (threadIdx.x < LL * 16) {
        B1[threadIdx.x] = eb1[threadIdx.x];
        W2[threadIdx.x] = ew2[threadIdx.x];
    }
    if (threadIdx.x < LL) B2[threadIdx.x] = eb2[threadIdx.x];
    __syncthreads();

    int p = blockIdx.x * blockDim.x + threadIdx.x;   // EE % 256 == 0
    int e = d_perm[p];
    d_srcp[p] = ei[e];                   // coalesced store, L2-hot random read
    float a0 = ea[e * 3 + 0];
    float a1 = ea[e * 3 + 1];
    float a2 = ea[e * 3 + 2];
#pragma unroll
    for (int l = 0; l < LL; l++) {
        float z = B2[l];
#pragma unroll
        for (int k = 0; k < 16; k++) {
            float hk = B1[l * 16 + k];
            hk = fmaf(a0, W1[l * 48 + 0 * 16 + k], hk);
            hk = fmaf(a1, W1[l * 48 + 1 * 16 + k], hk);
            hk = fmaf(a2, W1[l * 48 + 2 * 16 + k], hk);
            z = fmaf(fmaxf(hk, 0.f), W2[l * 16 + k], z);
        }
        d_gcsr[l * EE + p] = 1.f / (1.f + __expf(-z));
    }
}

// ---------------------------------------------------------------------------
// Fused layer: warp per 4 dst nodes (validated R9 structure; e1 = e0 + deg).
// ---------------------------------------------------------------------------
__global__ void __launch_bounds__(256)
layer_kernel(const float4* __restrict__ hin4,
             float* __restrict__ hout,
             const float* __restrict__ gcsr_l,
             const float* __restrict__ nw,
             const float* __restrict__ nb,
             const float* __restrict__ g,
             const float* __restrict__ b) {
    __shared__ float4 Wq[32 * 64];         // 32 KB  (k-interleaved float4)
    __shared__ float nbs[HH], gs[HH], bs[HH];
    __shared__ float ins[8][4 * 2 * HH];   // per-warp, 4 nodes x [h(64),agg(64)]

    {
        float* Wqf = (float*)Wq;
        for (int i = threadIdx.x; i < 2 * HH * HH; i += blockDim.x) {
            int k = i >> 6;
            int j = i & 63;
            Wqf[((k >> 2) * 64 + j) * 4 + (k & 3)] = nw[i];
        }
    }
    if (threadIdx.x < HH) {
        nbs[threadIdx.x] = nb[threadIdx.x];
        gs[threadIdx.x]  = g[threadIdx.x];
        bs[threadIdx.x]  = b[threadIdx.x];
    }
    __syncthreads();

    int warp = threadIdx.x >> 5;
    int lane = threadIdx.x & 31;
    int qtr  = lane >> 3;
    int ql   = lane & 7;

    float* insw = &ins[warp][0];
    float4* ins4 = (float4*)insw;
    uint32_t insAddr = (uint32_t)__cvta_generic_to_shared(insw);
    uint32_t wBase   = (uint32_t)__cvta_generic_to_shared(Wq) + lane * 16;

    for (int nd0 = (blockIdx.x * 8 + warp) * 4; nd0 < NN; nd0 += gridDim.x * 32) {
        // ---- Phase A: gather 4 nodes ----
#pragma unroll
        for (int nloc = 0; nloc < 4; nloc++) {
            int nd = nd0 + nloc;
            int e0 = d_off[nd];
            int e1 = e0 + d_deg[nd];

            float a0 = 0.f, a1 = 0.f, a2 = 0.f, a3 = 0.f;
            float a4 = 0.f, a5 = 0.f, a6 = 0.f, a7 = 0.f;
            float cw = 0.f;

            for (int base = e0; base < e1; base += 32) {
                int n = e1 - base;
                if (n > 32) n = 32;
                int   s = 0;
                float w = 0.f;
                if (lane < n) {
                    s = d_srcp[base + lane];
                    w = gcsr_l[base + lane];
                }
                cw += w;
                for (int i = 0; i < n; i += 8) {
                    int idx0 = i + qtr;
                    int idx1 = i + 4 + qtr;
                    int   s0 = __shfl_sync(0xffffffffu, s, idx0);
                    float w0 = __shfl_sync(0xffffffffu, w, idx0);
                    int   s1 = __shfl_sync(0xffffffffu, s, idx1);
                    float w1 = __shfl_sync(0xffffffffu, w, idx1);
                    float4 u0 = hin4[s0 * 16 + ql];
                    float4 u1 = hin4[s0 * 16 + 8 + ql];
                    float4 v0 = hin4[s1 * 16 + ql];
                    float4 v1 = hin4[s1 * 16 + 8 + ql];
                    a0 = fmaf(u0.x, w0, a0); a1 = fmaf(u0.y, w0, a1);
                    a2 = fmaf(u0.z, w0, a2); a3 = fmaf(u0.w, w0, a3);
                    a4 = fmaf(u1.x, w0, a4); a5 = fmaf(u1.y, w0, a5);
                    a6 = fmaf(u1.z, w0, a6); a7 = fmaf(u1.w, w0, a7);
                    a0 = fmaf(v0.x, w1, a0); a1 = fmaf(v0.y, w1, a1);
                    a2 = fmaf(v0.z, w1, a2); a3 = fmaf(v0.w, w1, a3);
                    a4 = fmaf(v1.x, w1, a4); a5 = fmaf(v1.y, w1, a5);
                    a6 = fmaf(v1.z, w1, a6); a7 = fmaf(v1.w, w1, a7);
                }
            }
#pragma unroll
            for (int o = 8; o <= 16; o <<= 1) {
                a0 += __shfl_xor_sync(0xffffffffu, a0, o);
                a1 += __shfl_xor_sync(0xffffffffu, a1, o);
                a2 += __shfl_xor_sync(0xffffffffu, a2, o);
                a3 += __shfl_xor_sync(0xffffffffu, a3, o);
                a4 += __shfl_xor_sync(0xffffffffu, a4, o);
                a5 += __shfl_xor_sync(0xffffffffu, a5, o);
                a6 += __shfl_xor_sync(0xffffffffu, a6, o);
                a7 += __shfl_xor_sync(0xffffffffu, a7, o);
            }
#pragma unroll
            for (int o = 16; o > 0; o >>= 1)
                cw += __shfl_xor_sync(0xffffffffu, cw, o);

            float inv = 1.f / fmaxf(cw, 1e-12f);
            if (lane < 16)
                ins4[nloc * 32 + lane] = hin4[(size_t)nd * 16 + lane];
            if (qtr == 0)
                ins4[nloc * 32 + 16 + ql] =
                    make_float4(a0 * inv, a1 * inv, a2 * inv, a3 * inv);
            else if (qtr == 1)
                ins4[nloc * 32 + 16 + 8 + ql] =
                    make_float4(a4 * inv, a5 * inv, a6 * inv, a7 * inv);
            __syncwarp();
        }

        // ---- Phase B: joint MLP (FFMA2) ----
        unsigned long long aA0 = 0, aA1 = 0, aA2 = 0, aA3 = 0;
        unsigned long long aB0 = 0, aB1 = 0, aB2 = 0, aB3 = 0;
        uint32_t wAddr = wBase;
#pragma unroll
        for (int t = 0; t < 32; t++) {
            unsigned long long wa0, wa1, wb0, wb1;
            ldsv2u64(wAddr, wa0, wa1);
            ldsv2u64(wAddr + 512, wb0, wb1);
            unsigned long long x0, x1;
            ldsv2u64(insAddr + 0 * 512 + t * 16, x0, x1);
            ffma2(aA0, x0, wa0); ffma2(aA0, x1, wa1);
            ffma2(aB0, x0, wb0); ffma2(aB0, x1, wb1);
            ldsv2u64(insAddr + 1 * 512 + t * 16, x0, x1);
            ffma2(aA1, x0, wa0); ffma2(aA1, x1, wa1);
            ffma2(aB1, x0, wb0); ffma2(aB1, x1, wb1);
            ldsv2u64(insAddr + 2 * 512 + t * 16, x0, x1);
            ffma2(aA2, x0, wa0); ffma2(aA2, x1, wa1);
            ffma2(aB2, x0, wb0); ffma2(aB2, x1, wb1);
            ldsv2u64(insAddr + 3 * 512 + t * 16, x0, x1);
            ffma2(aA3, x0, wa0); ffma2(aA3, x1, wa1);
            ffma2(aB3, x0, wb0); ffma2(aB3, x1, wb1);
            wAddr += 1024;
        }

        float o0n[4], o1n[4];
        o0n[0] = pairsum(aA0); o0n[1] = pairsum(aA1);
        o0n[2] = pairsum(aA2); o0n[3] = pairsum(aA3);
        o1n[0] = pairsum(aB0); o1n[1] = pairsum(aB1);
        o1n[2] = pairsum(aB2); o1n[3] = pairsum(aB3);

        float bias0 = nbs[lane];
        float bias1 = nbs[lane + 32];

        // ---- Phase C: residual + LN per node ----
#pragma unroll
        for (int nloc = 0; nloc < 4; nloc++) {
            int nd = nd0 + nloc;
            float hl = insw[nloc * 128 + lane];
            float hh = insw[nloc * 128 + 32 + lane];
            float v0 = hl + fmaxf(o0n[nloc] + bias0, 0.f);
            float v1 = hh + fmaxf(o1n[nloc] + bias1, 0.f);

            float s1 = v0 + v1;
#pragma unroll
            for (int o = 16; o > 0; o >>= 1)
                s1 += __shfl_xor_sync(0xffffffffu, s1, o);
            float mu = s1 * (1.f / HH);
            float t0 = v0 - mu, t1 = v1 - mu;
            float s2 = t0 * t0 + t1 * t1;
#pragma unroll
            for (int o = 16; o > 0; o >>= 1)
                s2 += __shfl_xor_sync(0xffffffffu, s2, o);
            float var = s2 * (1.f / HH);
            float r = rsqrtf(var + 1e-5f);

            hout[nd * HH + lane]      = t0 * r * gs[lane]      + bs[lane];
            hout[nd * HH + 32 + lane] = t1 * r * gs[lane + 32] + bs[lane + 32];
        }
        __syncwarp();
    }
}

// ---------------------------------------------------------------------------
// Head: out = relu(h @ hw1 + hb1) @ hw2 + hb2
// ---------------------------------------------------------------------------
__global__ void head_kernel(const float* __restrict__ hsrc,
                            const float* __restrict__ hw1,
                            const float* __restrict__ hb1,
                            const float* __restrict__ hw2,
                            const float* __restrict__ hb2,
                            float* __restrict__ out) {
    __shared__ float W1[HH * 32];
    __shared__ float b1s[32], w2s[32];
    for (int i = threadIdx.x; i < HH * 32; i += blockDim.x) W1[i] = hw1[i];
    if (threadIdx.x < 32) {
        b1s[threadIdx.x] = hb1[threadIdx.x];
        w2s[threadIdx.x] = hw2[threadIdx.x];
    }
    __syncthreads();

    int lane = threadIdx.x & 31;
    int warp = threadIdx.x >> 5;
    float bb2 = hb2[0];

    for (int node = blockIdx.x * 8 + warp; node < NN; node += gridDim.x * 8) {
        float hlo = hsrc[node * HH + lane];
        float hhi = hsrc[node * HH + 32 + lane];
        float acc = b1s[lane];
#pragma unroll
        for (int k = 0; k < 32; k++) {
            float hk = __shfl_sync(0xffffffffu, hlo, k);
            acc = fmaf(hk, W1[k * 32 + lane], acc);
        }
#pragma unroll
        for (int k = 0; k < 32; k++) {
            float hk = __shfl_sync(0xffffffffu, hhi, k);
            acc = fmaf(hk, W1[(32 + k) * 32 + lane], acc);
        }
        float p = fmaxf(acc, 0.f) * w2s[lane];
#pragma unroll
        for (int o = 16; o > 0; o >>= 1)
            p += __shfl_xor_sync(0xffffffffu, p, o);
        if (lane == 0) out[node] = p + bb2;
    }
}

// ---------------------------------------------------------------------------
extern "C" void kernel_launch(void* const* d_in, const int* in_sizes, int n_in,
                              void* d_out, int out_size) {
    const float* x   = (const float*)d_in[0];
    const int*   ei  = (const int*)  d_in[1];
    const float* ea  = (const float*)d_in[2];
    const float* Wp  = (const float*)d_in[3];
    const float* bp  = (const float*)d_in[4];
    const float* ew1 = (const float*)d_in[5];
    const float* eb1 = (const float*)d_in[6];
    const float* ew2 = (const float*)d_in[7];
    const float* eb2 = (const float*)d_in[8];
    const float* nw  = (const float*)d_in[9];
    const float* nb  = (const float*)d_in[10];
    const float* lng = (const float*)d_in[11];
    const float* lnb = (const float*)d_in[12];
    const float* hw1 = (const float*)d_in[13];
    const float* hb1 = (const float*)d_in[14];
    const float* hw2 = (const float*)d_in[15];
    const float* hb2 = (const float*)d_in[16];
    float* out = (float*)d_out;

    void* degPtr = nullptr; void* totPtr = nullptr;
    cudaGetSymbolAddress(&degPtr, d_deg);
    cudaGetSymbolAddress(&totPtr, d_total);
    float* hA = nullptr; float* hB = nullptr; float* gcsr = nullptr;
    cudaGetSymbolAddress((void**)&hA, d_hA);
    cudaGetSymbolAddress((void**)&hB, d_hB);
    cudaGetSymbolAddress((void**)&gcsr, d_gcsr);

    // Static side stream + events, created on the first (uncaptured) call.
    static cudaStream_t sProj = nullptr;
    static cudaEvent_t evRoot = nullptr, evProj = nullptr;
    if (sProj == nullptr) {
        cudaStreamCreateWithFlags(&sProj, cudaStreamNonBlocking);
        cudaEventCreateWithFlags(&evRoot, cudaEventDisableTiming);
        cudaEventCreateWithFlags(&evProj, cudaEventDisableTiming);
    }

    // Fork: proj runs on side stream, overlapping the CSR build chain.
    cudaEventRecord(evRoot, 0);
    cudaStreamWaitEvent(sProj, evRoot, 0);
    proj_kernel<<<(NN * HH + 255) / 256, 256, 0, sProj>>>(x, Wp, bp);
    cudaEventRecord(evProj, sProj);

    cudaMemsetAsync(degPtr, 0, (size_t)NN * sizeof(int));
    cudaMemsetAsync(totPtr, 0, sizeof(int));
    count_kernel<<<(QS + 255) / 256, 256>>>(ei);
    alloc_kernel<<<(NN + 255) / 256, 256>>>();
    fill_kernel<<<(QS + 255) / 256, 256>>>(ei);
    gatecsr_kernel<<<EE / 256, 256>>>(ei, ea, ew1, eb1, ew2, eb2);

    // Join: layers need both proj (hA) and gates/CSR.
    cudaStreamWaitEvent(0, evProj, 0);

    for (int l = 0; l < LL; l++) {
        const float* hin  = (l & 1) ? hB : hA;
        float*       hout = (l & 1) ? hA : hB;
        layer_kernel<<<592, 256>>>((const float4*)hin, hout,
                                   gcsr + (size_t)l * EE,
                                   nw + l * 2 * HH * HH, nb + l * HH,
                                   lng + l * HH, lnb + l * HH);
    }

    head_kernel<<<592, 256>>>(hB, hw1, hb1, hw2, hb2, out);
}

// round 17
// speedup vs baseline: 1.0053x; 1.0053x over previous
#include <cuda_runtime.h>
#include <math.h>
#include <stdint.h>

#define NN 50000
#define EE 800000
#define FIN 10
#define HH 64
#define LL 3

__device__ float  d_hA[NN * HH];
__device__ float  d_hB[NN * HH];
__device__ int    d_deg[NN];
__device__ int    d_off[NN];           // bucket start per node (unordered)
__device__ int    d_cur[NN];
__device__ int    d_total;
__device__ int    d_perm[EE];          // original edge id per CSR slot
__device__ float2 d_sg[LL * EE];       // per layer, per CSR slot: {src_bits, gate}

// ---------------------------------------------------------------------------
// packed f32x2 helpers
// ---------------------------------------------------------------------------
__device__ __forceinline__ void ldsv2u64(uint32_t addr,
                                         unsigned long long& a,
                                         unsigned long long& b) {
    asm volatile("ld.shared.v2.u64 {%0,%1}, [%2];"
                 : "=l"(a), "=l"(b) : "r"(addr));
}
__device__ __forceinline__ void ffma2(unsigned long long& d,
                                      unsigned long long a,
                                      unsigned long long b) {
    asm("fma.rn.f32x2 %0, %1, %2, %0;" : "+l"(d) : "l"(a), "l"(b));
}
__device__ __forceinline__ float pairsum(unsigned long long v) {
    uint32_t lo, hi;
    asm("mov.b64 {%0,%1}, %2;" : "=r"(lo), "=r"(hi) : "l"(v));
    return __uint_as_float(lo) + __uint_as_float(hi);
}

// ---------------------------------------------------------------------------
// h = relu(x @ Wp + bp)
// ---------------------------------------------------------------------------
__global__ void proj_kernel(const float* __restrict__ x,
                            const float* __restrict__ Wp,
                            const float* __restrict__ bp) {
    __shared__ float Ws[FIN * HH];
    __shared__ float bs[HH];
    for (int i = threadIdx.x; i < FIN * HH; i += blockDim.x) Ws[i] = Wp[i];
    if (threadIdx.x < HH) bs[threadIdx.x] = bp[threadIdx.x];
    __syncthreads();

    int idx = blockIdx.x * blockDim.x + threadIdx.x;
    if (idx >= NN * HH) return;
    int i = idx >> 6;
    int j = idx & 63;
    float acc = bs[j];
#pragma unroll
    for (int k = 0; k < FIN; k++) acc = fmaf(x[i * FIN + k], Ws[k * HH + j], acc);
    d_hA[idx] = fmaxf(acc, 0.f);
}

// ---------------------------------------------------------------------------
// CSR build: count -> alloc (warp-aggregated atomic) -> fill (perm only)
// ---------------------------------------------------------------------------
__global__ void count_kernel(const int* __restrict__ ei) {
    int e = blockIdx.x * blockDim.x + threadIdx.x;
    if (e >= EE) return;
    atomicAdd(&d_deg[ei[EE + e]], 1);
}

__global__ void alloc_kernel() {
    int nd = blockIdx.x * blockDim.x + threadIdx.x;
    int lane = threadIdx.x & 31;
    int deg = (nd < NN) ? d_deg[nd] : 0;
    int sc = deg;
#pragma unroll
    for (int o = 1; o < 32; o <<= 1) {
        int v = __shfl_up_sync(0xffffffffu, sc, o);
        if (lane >= o) sc += v;
    }
    int wsum = __shfl_sync(0xffffffffu, sc, 31);
    int base = 0;
    if (lane == 31) base = atomicAdd(&d_total, wsum);
    base = __shfl_sync(0xffffffffu, base, 31);
    if (nd < NN) {
        int excl = base + sc - deg;
        d_off[nd] = excl;
        d_cur[nd] = excl;
    }
}

__global__ void fill_kernel(const int* __restrict__ ei) {
    int e = blockIdx.x * blockDim.x + threadIdx.x;
    if (e >= EE) return;
    int d = ei[EE + e];
    int p = atomicAdd(&d_cur[d], 1);
    d_perm[p] = e;
}

// ---------------------------------------------------------------------------
// Gates for all 3 layers in CSR order, packed with src: d_sg[l][p].
// ---------------------------------------------------------------------------
__global__ void gatecsr_kernel(const int* __restrict__ ei,
                               const float* __restrict__ ea,
                               const float* __restrict__ ew1,
                               const float* __restrict__ eb1,
                               const float* __restrict__ ew2,
                               const float* __restrict__ eb2) {
    __shared__ float W1[LL * 3 * 16];
    __shared__ float B1[LL * 16];
    __shared__ float W2[LL * 16];
    __shared__ float B2[LL];
    for (int i = threadIdx.x; i < LL * 3 * 16; i += blockDim.x) W1[i] = ew1[i];
    if (threadIdx.x < LL * 16) {
        B1[threadIdx.x] = eb1[threadIdx.x];
        W2[threadIdx.x] = ew2[threadIdx.x];
    }
    if (threadIdx.x < LL) B2[threadIdx.x] = eb2[threadIdx.x];
    __syncthreads();

    int p = blockIdx.x * blockDim.x + threadIdx.x;   // EE % 256 == 0
    int e = d_perm[p];
    float sbits = __int_as_float(ei[e]);             // src (L2-hot random read)
    float a0 = ea[e * 3 + 0];
    float a1 = ea[e * 3 + 1];
    float a2 = ea[e * 3 + 2];
#pragma unroll
    for (int l = 0; l < LL; l++) {
        float z = B2[l];
#pragma unroll
        for (int k = 0; k < 16; k++) {
            float hk = B1[l * 16 + k];
            hk = fmaf(a0, W1[l * 48 + 0 * 16 + k], hk);
            hk = fmaf(a1, W1[l * 48 + 1 * 16 + k], hk);
            hk = fmaf(a2, W1[l * 48 + 2 * 16 + k], hk);
            z = fmaf(fmaxf(hk, 0.f), W2[l * 16 + k], z);
        }
        float g = 1.f / (1.f + __expf(-z));
        d_sg[l * EE + p] = make_float2(sbits, g);
    }
}

// ---------------------------------------------------------------------------
// Fused layer: warp per 4 dst nodes (validated R9 structure).
// Phase A prologue now a single LDG.64 per edge slot (packed src+gate).
// ---------------------------------------------------------------------------
__global__ void __launch_bounds__(256)
layer_kernel(const float4* __restrict__ hin4,
             float* __restrict__ hout,
             const float2* __restrict__ sgl,
             const float* __restrict__ nw,
             const float* __restrict__ nb,
             const float* __restrict__ g,
             const float* __restrict__ b) {
    __shared__ float4 Wq[32 * 64];         // 32 KB  (k-interleaved float4)
    __shared__ float nbs[HH], gs[HH], bs[HH];
    __shared__ float ins[8][4 * 2 * HH];   // per-warp, 4 nodes x [h(64),agg(64)]

    {
        float* Wqf = (float*)Wq;
        for (int i = threadIdx.x; i < 2 * HH * HH; i += blockDim.x) {
            int k = i >> 6;
            int j = i & 63;
            Wqf[((k >> 2) * 64 + j) * 4 + (k & 3)] = nw[i];
        }
    }
    if (threadIdx.x < HH) {
        nbs[threadIdx.x] = nb[threadIdx.x];
        gs[threadIdx.x]  = g[threadIdx.x];
        bs[threadIdx.x]  = b[threadIdx.x];
    }
    __syncthreads();

    int warp = threadIdx.x >> 5;
    int lane = threadIdx.x & 31;
    int qtr  = lane >> 3;
    int ql   = lane & 7;

    float* insw = &ins[warp][0];
    float4* ins4 = (float4*)insw;
    uint32_t insAddr = (uint32_t)__cvta_generic_to_shared(insw);
    uint32_t wBase   = (uint32_t)__cvta_generic_to_shared(Wq) + lane * 16;

    for (int nd0 = (blockIdx.x * 8 + warp) * 4; nd0 < NN; nd0 += gridDim.x * 32) {
        // ---- Phase A: gather 4 nodes ----
#pragma unroll
        for (int nloc = 0; nloc < 4; nloc++) {
            int nd = nd0 + nloc;
            int e0 = d_off[nd];
            int e1 = e0 + d_deg[nd];

            float a0 = 0.f, a1 = 0.f, a2 = 0.f, a3 = 0.f;
            float a4 = 0.f, a5 = 0.f, a6 = 0.f, a7 = 0.f;
            float cw = 0.f;

            for (int base = e0; base < e1; base += 32) {
                int n = e1 - base;
                if (n > 32) n = 32;
                int   s = 0;
                float w = 0.f;
                if (lane < n) {
                    float2 sg = sgl[base + lane];    // one LDG.64
                    s = __float_as_int(sg.x);
                    w = sg.y;
                }
                cw += w;
                for (int i = 0; i < n; i += 8) {
                    int idx0 = i + qtr;
                    int idx1 = i + 4 + qtr;
                    int   s0 = __shfl_sync(0xffffffffu, s, idx0);
                    float w0 = __shfl_sync(0xffffffffu, w, idx0);
                    int   s1 = __shfl_sync(0xffffffffu, s, idx1);
                    float w1 = __shfl_sync(0xffffffffu, w, idx1);
                    float4 u0 = hin4[s0 * 16 + ql];
                    float4 u1 = hin4[s0 * 16 + 8 + ql];
                    float4 v0 = hin4[s1 * 16 + ql];
                    float4 v1 = hin4[s1 * 16 + 8 + ql];
                    a0 = fmaf(u0.x, w0, a0); a1 = fmaf(u0.y, w0, a1);
                    a2 = fmaf(u0.z, w0, a2); a3 = fmaf(u0.w, w0, a3);
                    a4 = fmaf(u1.x, w0, a4); a5 = fmaf(u1.y, w0, a5);
                    a6 = fmaf(u1.z, w0, a6); a7 = fmaf(u1.w, w0, a7);
                    a0 = fmaf(v0.x, w1, a0); a1 = fmaf(v0.y, w1, a1);
                    a2 = fmaf(v0.z, w1, a2); a3 = fmaf(v0.w, w1, a3);
                    a4 = fmaf(v1.x, w1, a4); a5 = fmaf(v1.y, w1, a5);
                    a6 = fmaf(v1.z, w1, a6); a7 = fmaf(v1.w, w1, a7);
                }
            }
#pragma unroll
            for (int o = 8; o <= 16; o <<= 1) {
                a0 += __shfl_xor_sync(0xffffffffu, a0, o);
                a1 += __shfl_xor_sync(0xffffffffu, a1, o);
                a2 += __shfl_xor_sync(0xffffffffu, a2, o);
                a3 += __shfl_xor_sync(0xffffffffu, a3, o);
                a4 += __shfl_xor_sync(0xffffffffu, a4, o);
                a5 += __shfl_xor_sync(0xffffffffu, a5, o);
                a6 += __shfl_xor_sync(0xffffffffu, a6, o);
                a7 += __shfl_xor_sync(0xffffffffu, a7, o);
            }
#pragma unroll
            for (int o = 16; o > 0; o >>= 1)
                cw += __shfl_xor_sync(0xffffffffu, cw, o);

            float inv = 1.f / fmaxf(cw, 1e-12f);
            if (lane < 16)
                ins4[nloc * 32 + lane] = hin4[(size_t)nd * 16 + lane];
            if (qtr == 0)
                ins4[nloc * 32 + 16 + ql] =
                    make_float4(a0 * inv, a1 * inv, a2 * inv, a3 * inv);
            else if (qtr == 1)
                ins4[nloc * 32 + 16 + 8 + ql] =
                    make_float4(a4 * inv, a5 * inv, a6 * inv, a7 * inv);
            __syncwarp();
        }

        // ---- Phase B: joint MLP (FFMA2) ----
        unsigned long long aA0 = 0, aA1 = 0, aA2 = 0, aA3 = 0;
        unsigned long long aB0 = 0, aB1 = 0, aB2 = 0, aB3 = 0;
        uint32_t wAddr = wBase;
#pragma unroll
        for (int t = 0; t < 32; t++) {
            unsigned long long wa0, wa1, wb0, wb1;
            ldsv2u64(wAddr, wa0, wa1);
            ldsv2u64(wAddr + 512, wb0, wb1);
            unsigned long long x0, x1;
            ldsv2u64(insAddr + 0 * 512 + t * 16, x0, x1);
            ffma2(aA0, x0, wa0); ffma2(aA0, x1, wa1);
            ffma2(aB0, x0, wb0); ffma2(aB0, x1, wb1);
            ldsv2u64(insAddr + 1 * 512 + t * 16, x0, x1);
            ffma2(aA1, x0, wa0); ffma2(aA1, x1, wa1);
            ffma2(aB1, x0, wb0); ffma2(aB1, x1, wb1);
            ldsv2u64(insAddr + 2 * 512 + t * 16, x0, x1);
            ffma2(aA2, x0, wa0); ffma2(aA2, x1, wa1);
            ffma2(aB2, x0, wb0); ffma2(aB2, x1, wb1);
            ldsv2u64(insAddr + 3 * 512 + t * 16, x0, x1);
            ffma2(aA3, x0, wa0); ffma2(aA3, x1, wa1);
            ffma2(aB3, x0, wb0); ffma2(aB3, x1, wb1);
            wAddr += 1024;
        }

        float o0n[4], o1n[4];
        o0n[0] = pairsum(aA0); o0n[1] = pairsum(aA1);
        o0n[2] = pairsum(aA2); o0n[3] = pairsum(aA3);
        o1n[0] = pairsum(aB0); o1n[1] = pairsum(aB1);
        o1n[2] = pairsum(aB2); o1n[3] = pairsum(aB3);

        float bias0 = nbs[lane];
        float bias1 = nbs[lane + 32];

        // ---- Phase C: residual + LN per node ----
#pragma unroll
        for (int nloc = 0; nloc < 4; nloc++) {
            int nd = nd0 + nloc;
            float hl = insw[nloc * 128 + lane];
            float hh = insw[nloc * 128 + 32 + lane];
            float v0 = hl + fmaxf(o0n[nloc] + bias0, 0.f);
            float v1 = hh + fmaxf(o1n[nloc] + bias1, 0.f);

            float s1 = v0 + v1;
#pragma unroll
            for (int o = 16; o > 0; o >>= 1)
                s1 += __shfl_xor_sync(0xffffffffu, s1, o);
            float mu = s1 * (1.f / HH);
            float t0 = v0 - mu, t1 = v1 - mu;
            float s2 = t0 * t0 + t1 * t1;
#pragma unroll
            for (int o = 16; o > 0; o >>= 1)
                s2 += __shfl_xor_sync(0xffffffffu, s2, o);
            float var = s2 * (1.f / HH);
            float r = rsqrtf(var + 1e-5f);

            hout[nd * HH + lane]      = t0 * r * gs[lane]      + bs[lane];
            hout[nd * HH + 32 + lane] = t1 * r * gs[lane + 32] + bs[lane + 32];
        }
        __syncwarp();
    }
}

// ---------------------------------------------------------------------------
// Head: out = relu(h @ hw1 + hb1) @ hw2 + hb2
// ---------------------------------------------------------------------------
__global__ void head_kernel(const float* __restrict__ hsrc,
                            const float* __restrict__ hw1,
                            const float* __restrict__ hb1,
                            const float* __restrict__ hw2,
                            const float* __restrict__ hb2,
                            float* __restrict__ out) {
    __shared__ float W1[HH * 32];
    __shared__ float b1s[32], w2s[32];
    for (int i = threadIdx.x; i < HH * 32; i += blockDim.x) W1[i] = hw1[i];
    if (threadIdx.x < 32) {
        b1s[threadIdx.x] = hb1[threadIdx.x];
        w2s[threadIdx.x] = hw2[threadIdx.x];
    }
    __syncthreads();

    int lane = threadIdx.x & 31;
    int warp = threadIdx.x >> 5;
    float bb2 = hb2[0];

    for (int node = blockIdx.x * 8 + warp; node < NN; node += gridDim.x * 8) {
        float hlo = hsrc[node * HH + lane];
        float hhi = hsrc[node * HH + 32 + lane];
        float acc = b1s[lane];
#pragma unroll
        for (int k = 0; k < 32; k++) {
            float hk = __shfl_sync(0xffffffffu, hlo, k);
            acc = fmaf(hk, W1[k * 32 + lane], acc);
        }
#pragma unroll
        for (int k = 0; k < 32; k++) {
            float hk = __shfl_sync(0xffffffffu, hhi, k);
            acc = fmaf(hk, W1[(32 + k) * 32 + lane], acc);
        }
        float p = fmaxf(acc, 0.f) * w2s[lane];
#pragma unroll
        for (int o = 16; o > 0; o >>= 1)
            p += __shfl_xor_sync(0xffffffffu, p, o);
        if (lane == 0) out[node] = p + bb2;
    }
}

// ---------------------------------------------------------------------------
extern "C" void kernel_launch(void* const* d_in, const int* in_sizes, int n_in,
                              void* d_out, int out_size) {
    const float* x   = (const float*)d_in[0];
    const int*   ei  = (const int*)  d_in[1];
    const float* ea  = (const float*)d_in[2];
    const float* Wp  = (const float*)d_in[3];
    const float* bp  = (const float*)d_in[4];
    const float* ew1 = (const float*)d_in[5];
    const float* eb1 = (const float*)d_in[6];
    const float* ew2 = (const float*)d_in[7];
    const float* eb2 = (const float*)d_in[8];
    const float* nw  = (const float*)d_in[9];
    const float* nb  = (const float*)d_in[10];
    const float* lng = (const float*)d_in[11];
    const float* lnb = (const float*)d_in[12];
    const float* hw1 = (const float*)d_in[13];
    const float* hb1 = (const float*)d_in[14];
    const float* hw2 = (const float*)d_in[15];
    const float* hb2 = (const float*)d_in[16];
    float* out = (float*)d_out;

    void* degPtr = nullptr; void* totPtr = nullptr;
    cudaGetSymbolAddress(&degPtr, d_deg);
    cudaGetSymbolAddress(&totPtr, d_total);
    float* hA = nullptr; float* hB = nullptr; float2* sg = nullptr;
    cudaGetSymbolAddress((void**)&hA, d_hA);
    cudaGetSymbolAddress((void**)&hB, d_hB);
    cudaGetSymbolAddress((void**)&sg, d_sg);

    // Static side stream + events, created on the first (uncaptured) call.
    static cudaStream_t sProj = nullptr;
    static cudaEvent_t evRoot = nullptr, evProj = nullptr;
    if (sProj == nullptr) {
        cudaStreamCreateWithFlags(&sProj, cudaStreamNonBlocking);
        cudaEventCreateWithFlags(&evRoot, cudaEventDisableTiming);
        cudaEventCreateWithFlags(&evProj, cudaEventDisableTiming);
    }

    // Fork: proj runs on side stream, overlapping the CSR build chain.
    cudaEventRecord(evRoot, 0);
    cudaStreamWaitEvent(sProj, evRoot, 0);
    proj_kernel<<<(NN * HH + 255) / 256, 256, 0, sProj>>>(x, Wp, bp);
    cudaEventRecord(evProj, sProj);

    cudaMemsetAsync(degPtr, 0, (size_t)NN * sizeof(int));
    cudaMemsetAsync(totPtr, 0, sizeof(int));
    count_kernel<<<(EE + 255) / 256, 256>>>(ei);
    alloc_kernel<<<(NN + 255) / 256, 256>>>();
    fill_kernel<<<(EE + 255) / 256, 256>>>(ei);
    gatecsr_kernel<<<EE / 256, 256>>>(ei, ea, ew1, eb1, ew2, eb2);

    // Join: layers need both proj (hA) and gates/CSR.
    cudaStreamWaitEvent(0, evProj, 0);

    for (int l = 0; l < LL; l++) {
        const float* hin  = (l & 1) ? hB : hA;
        float*       hout = (l & 1) ? hA : hB;
        layer_kernel<<<592, 256>>>((const float4*)hin, hout,
                                   sg + (size_t)l * EE,
                                   nw + l * 2 * HH * HH, nb + l * HH,
                                   lng + l * HH, lnb + l * HH);
    }

    head_kernel<<<592, 256>>>(hB, hw1, hb1, hw2, hb2, out);
}